// round 15
// baseline (speedup 1.0000x reference)
#include <cuda_runtime.h>
#include <cuda_fp16.h>
#include <cstdint>
#include <cstddef>

#define BATCH     131072
#define FDIM      512
#define F2DIM     256
#define OBJ_DIM   100000
#define PRED_DIM  2000
#define EPS_F     1e-5f
#define NTILE     2048            // 64-row tiles
#define LAG       512             // gemm tile lag (> max resident CTAs ~296)

// ---------------- device scratch (static, no allocation) ----------------
__device__ int   d_cnt_s[OBJ_DIM];
__device__ int   d_cnt_o[OBJ_DIM];
__device__ int   d_cnt_p[PRED_DIM + 16];
__device__ __align__(16) float d_sumb[3][FDIM];
__device__ __align__(16) float d_sqb [3][FDIM];
__device__ __align__(16) float d_cAg[3 * FDIM];
__device__ __align__(16) float d_cCg[3 * FDIM];
__device__ __align__(16) __half d_W4h[F2DIM * FDIM];         // fp16 W4, row-major [256][512]
__device__ __align__(16) __half d_Af[(size_t)BATCH * FDIM];  // fused fp16 A, 128 MB
__device__ __align__(16) __half d_yh[(size_t)BATCH * F2DIM]; // pre-BN layer-4 out, fp16, 64 MB
__device__ float d_sum4[F2DIM];
__device__ float d_sq4 [F2DIM];
__device__ int   d_flag[NTILE];   // gather-tile-ready flags

// ---------------- helpers ----------------
__device__ __forceinline__ uint32_t smem_u32(const void* p) {
    uint32_t a;
    asm("{ .reg .u64 t; cvta.to.shared.u64 t, %1; cvt.u32.u64 %0, t; }" : "=r"(a) : "l"(p));
    return a;
}
__device__ __forceinline__ void cp16(uint32_t dst, const void* src) {
    asm volatile("cp.async.cg.shared.global [%0], [%1], 16;" :: "r"(dst), "l"(src) : "memory");
}
__device__ __forceinline__ void cp_commit() {
    asm volatile("cp.async.commit_group;" ::: "memory");
}
__device__ __forceinline__ float relu_aff(float a, float w, float c) {
    return fmaxf(fmaf(a, w, c), 0.f);
}
__device__ __forceinline__ void ldsm4(uint32_t& r0, uint32_t& r1, uint32_t& r2, uint32_t& r3,
                                      uint32_t addr) {
    asm volatile("ldmatrix.sync.aligned.m8n8.x4.shared.b16 {%0,%1,%2,%3}, [%4];"
                 : "=r"(r0), "=r"(r1), "=r"(r2), "=r"(r3) : "r"(addr));
}
__device__ __forceinline__ void mma16816(float* d, uint32_t a0, uint32_t a1, uint32_t a2,
                                         uint32_t a3, uint32_t b0, uint32_t b1) {
    asm("mma.sync.aligned.m16n8k16.row.col.f32.f16.f16.f32 "
        "{%0,%1,%2,%3}, {%4,%5,%6,%7}, {%8,%9}, {%0,%1,%2,%3};\n"
        : "+f"(d[0]), "+f"(d[1]), "+f"(d[2]), "+f"(d[3])
        : "r"(a0), "r"(a1), "r"(a2), "r"(a3), "r"(b0), "r"(b1));
}

// ---------------- kernel 0: index histograms + W4 -> fp16 ----------------
__global__ void k_hist(const int* __restrict__ subj, const int* __restrict__ obj,
                       const int* __restrict__ predi, const float* __restrict__ W4) {
    int i = blockIdx.x * blockDim.x + threadIdx.x;
    atomicAdd(&d_cnt_s[subj[i]], 1);
    atomicAdd(&d_cnt_o[obj[i]], 1);
    atomicAdd(&d_cnt_p[predi[i]], 1);
    d_W4h[i] = __float2half_rn(W4[i]);
}

// ---------------- kernel 1: count-weighted column stats ----------------
__global__ void __launch_bounds__(256) k_cs(const float* __restrict__ W1,
                                            const float* __restrict__ W2,
                                            const float* __restrict__ W3,
                                            int S1, int S2) {
    const float* W; const int* cnt; int sel, bid, nblk, R;
    if ((int)blockIdx.x < S1)      { W = W1; cnt = d_cnt_s; sel = 0; bid = blockIdx.x;      nblk = S1;             R = OBJ_DIM; }
    else if ((int)blockIdx.x < S2) { W = W2; cnt = d_cnt_o; sel = 1; bid = blockIdx.x - S1; nblk = S2 - S1;        R = OBJ_DIM; }
    else                           { W = W3; cnt = d_cnt_p; sel = 2; bid = blockIdx.x - S2; nblk = gridDim.x - S2; R = PRED_DIM; }
    const int grp = threadIdx.x >> 7;          // 0..1 : independent row stream
    const int t   = threadIdx.x & 127;
    const int sid  = bid * 2 + grp;
    const int step = nblk * 16;
    float4 s = make_float4(0.f, 0.f, 0.f, 0.f);
    float4 q = make_float4(0.f, 0.f, 0.f, 0.f);
    int base = sid * 8;
    int4 ca, cb;
    if (base < R) { ca = *(const int4*)(cnt + base); cb = *(const int4*)(cnt + base + 4); }
    for (; base < R; base += step) {
        int4 na, nb;
        if (base + step < R) {
            na = *(const int4*)(cnt + base + step);
            nb = *(const int4*)(cnt + base + step + 4);
        }
        int cc[8] = {ca.x, ca.y, ca.z, ca.w, cb.x, cb.y, cb.z, cb.w};
        float4 v[8];
        #pragma unroll
        for (int u = 0; u < 8; u++)
            if (cc[u]) v[u] = __ldg((const float4*)(W + (size_t)(base + u) * FDIM) + t);
        #pragma unroll
        for (int u = 0; u < 8; u++) {
            if (cc[u]) {
                float fc = (float)cc[u];
                s.x += fc * v[u].x; s.y += fc * v[u].y; s.z += fc * v[u].z; s.w += fc * v[u].w;
                q.x += fc * v[u].x * v[u].x; q.y += fc * v[u].y * v[u].y;
                q.z += fc * v[u].z * v[u].z; q.w += fc * v[u].w * v[u].w;
            }
        }
        ca = na; cb = nb;
    }
    int cb0 = t * 4;
    atomicAdd(&d_sumb[sel][cb0 + 0], s.x);
    atomicAdd(&d_sumb[sel][cb0 + 1], s.y);
    atomicAdd(&d_sumb[sel][cb0 + 2], s.z);
    atomicAdd(&d_sumb[sel][cb0 + 3], s.w);
    atomicAdd(&d_sqb[sel][cb0 + 0], q.x);
    atomicAdd(&d_sqb[sel][cb0 + 1], q.y);
    atomicAdd(&d_sqb[sel][cb0 + 2], q.z);
    atomicAdd(&d_sqb[sel][cb0 + 3], q.w);
}

// ---------------- kernel 2: BN-relu affine coefficients (tiny) ----------------
__global__ void k_coef(const float* __restrict__ g1, const float* __restrict__ be1,
                       const float* __restrict__ g2, const float* __restrict__ be2,
                       const float* __restrict__ g3, const float* __restrict__ be3) {
    int t = threadIdx.x;  // 512
    const float* G[3]  = {g1, g2, g3};
    const float* BE[3] = {be1, be2, be3};
    #pragma unroll
    for (int b = 0; b < 3; b++) {
        float m = d_sumb[b][t] * (1.0f / BATCH);
        float v = d_sqb[b][t] * (1.0f / BATCH) - m * m;
        float a = G[b][t] * rsqrtf(v + EPS_F);
        d_cAg[b * FDIM + t] = a;
        d_cCg[b * FDIM + t] = BE[b][t] - a * m;
    }
}

// ---------------- kernel 3: FUSED gather->flag->GEMM (flag-pipelined CTAs) ----------------
// CTA j < NTILE: gather 64-row tile j (proven cp.async ring), set d_flag[j].
// CTA j >= LAG: spin on d_flag[j-LAG], then GEMM tile j-LAG (64 rows x 256 cols).
// Gather smem: ring 3 x 24576 = 73728, idx at 73728..74496.
// Gemm smem (reused after gather drains): 2 stages x (A 9216 + B 36864) = 92160,
// colsum @92160, colsq @93184. Total 94208 -> 2 CTAs/SM.
#define GG_STGB  24576
#define GG_IDX   73728
#define GM_A_SZ  (64 * 144)              // 9216
#define GM_STG   (GM_A_SZ + 256 * 144)   // 46080
#define GM_SUM   92160
#define GM_SQ    93184
#define GG_SMEM  94208

__global__ void __launch_bounds__(256, 2) k_gg(
    const int* __restrict__ subj, const int* __restrict__ obj, const int* __restrict__ predi,
    const float* __restrict__ W1, const float* __restrict__ W2, const float* __restrict__ W3)
{
    extern __shared__ char sg[];
    const uint32_t smb = smem_u32(sg);
    const int j = blockIdx.x;
    const int tid = threadIdx.x, lane = tid & 31, wid = tid >> 5;

    // ===== phase 1: gather tile j =====
    if (j < NTILE) {
        int* idxs = (int*)(sg + GG_IDX);           // [3][64]
        const int i0 = j * 64;
        if (tid < 64) {
            idxs[tid]       = subj[i0 + tid];
            idxs[64 + tid]  = obj[i0 + tid];
            idxs[128 + tid] = predi[i0 + tid];
        }
        const int c4 = tid & 127;
        const int rs0 = tid >> 7;          // 0..1
        const int k0 = c4 * 4;
        const float4 A1 = *(const float4*)&d_cAg[k0],            C1 = *(const float4*)&d_cCg[k0];
        const float4 A2 = *(const float4*)&d_cAg[512 + k0],      C2 = *(const float4*)&d_cCg[512 + k0];
        const float4 A3 = *(const float4*)&d_cAg[1024 + k0],     C3 = *(const float4*)&d_cCg[1024 + k0];
        __syncthreads();

        auto issue = [&](int s) {
            uint32_t dstb = smb + (s % 3) * GG_STGB;
            #pragma unroll
            for (int u = 0; u < 6; u++) {
                int lin = tid + 256 * u;            // 0..1535 float4 slots
                int ris = lin / 384;
                int rem = lin - ris * 384;
                int tab = rem >> 7;
                int cc  = rem & 127;
                int gi  = idxs[tab * 64 + s * 4 + ris];
                const float* Wt = (tab == 0) ? W1 : (tab == 1) ? W2 : W3;
                cp16(dstb + lin * 16, Wt + (size_t)gi * FDIM + cc * 4);
            }
            cp_commit();
        };

        issue(0); issue(1);
        #pragma unroll 1
        for (int s = 0; s < 16; s++) {
            if (s + 2 < 16) issue(s + 2);
            if (s < 14)       asm volatile("cp.async.wait_group 2;" ::: "memory");
            else if (s == 14) asm volatile("cp.async.wait_group 1;" ::: "memory");
            else              asm volatile("cp.async.wait_group 0;" ::: "memory");
            __syncthreads();
            const float4* st4 = (const float4*)(sg + (s % 3) * GG_STGB);
            #pragma unroll
            for (int rr = 0; rr < 2; rr++) {
                int ris = rs0 + rr * 2;
                int row = i0 + s * 4 + ris;
                float4 w1 = st4[ris * 384 + c4];
                float4 w2 = st4[ris * 384 + 128 + c4];
                float4 w3 = st4[ris * 384 + 256 + c4];
                float f0 = relu_aff(A1.x, w1.x, C1.x) + relu_aff(A2.x, w2.x, C2.x) + relu_aff(A3.x, w3.x, C3.x);
                float f1 = relu_aff(A1.y, w1.y, C1.y) + relu_aff(A2.y, w2.y, C2.y) + relu_aff(A3.y, w3.y, C3.y);
                float f2 = relu_aff(A1.z, w1.z, C1.z) + relu_aff(A2.z, w2.z, C2.z) + relu_aff(A3.z, w3.z, C3.z);
                float f3 = relu_aff(A1.w, w1.w, C1.w) + relu_aff(A2.w, w2.w, C2.w) + relu_aff(A3.w, w3.w, C3.w);
                __half2 h0 = __floats2half2_rn(f0, f1);
                __half2 h1 = __floats2half2_rn(f2, f3);
                uint2 u;
                u.x = *(unsigned*)&h0;
                u.y = *(unsigned*)&h1;
                *(uint2*)(d_Af + (size_t)row * FDIM + k0) = u;
            }
            __syncthreads();
        }
        __threadfence();                 // make A tile visible device-wide
        __syncthreads();
        if (tid == 0) atomicExch(&d_flag[j], 1);
    }

    // ===== phase 2: GEMM tile t = j - LAG =====
    if (j >= LAG) {
        const int t = j - LAG;
        if (tid == 0) {
            while (atomicAdd(&d_flag[t], 0) == 0) __nanosleep(64);
            __threadfence();
        }
        __syncthreads();

        float* colsum = (float*)(sg + GM_SUM);   // [256]
        float* colsq  = (float*)(sg + GM_SQ);    // [256]
        colsum[tid] = 0.f;
        colsq[tid] = 0.f;

        const int i0 = t * 64;
        const int wm = wid >> 2, wn = wid & 3, g = lane >> 2, tig = lane & 3;

        auto issueG = [&](int c) {
            if (c < 8) {
                uint32_t base = smb + (c & 1) * GM_STG;
                #pragma unroll
                for (int u = 0; u < 2; u++) {        // A: 64 rows x 64 halfs = 512 slots
                    int idx = tid + 256 * u;
                    int row = idx >> 3, o = idx & 7;
                    cp16(base + row * 144 + o * 16,
                         d_Af + (size_t)(i0 + row) * FDIM + c * 64 + o * 8);
                }
                #pragma unroll
                for (int u = 0; u < 8; u++) {        // B: 256 rows x 64 halfs = 2048 slots
                    int idx = tid + 256 * u;
                    int n = idx >> 3, o = idx & 7;
                    cp16(base + GM_A_SZ + n * 144 + o * 16,
                         d_W4h + n * FDIM + c * 64 + o * 8);
                }
            }
            cp_commit();
        };

        float acc[2][8][4];
        #pragma unroll
        for (int mt = 0; mt < 2; mt++)
            #pragma unroll
            for (int nt = 0; nt < 8; nt++)
                #pragma unroll
                for (int u = 0; u < 4; u++) acc[mt][nt][u] = 0.f;

        const int lm_r = lane & 15;
        const int lm_c = (lane >> 4) * 16;
        const uint32_t a_off = (wm * 32 + lm_r) * 144 + lm_c;
        const uint32_t b_off = GM_A_SZ + (wn * 64 + lm_r) * 144 + lm_c;

        issueG(0); issueG(1);
        #pragma unroll 1
        for (int c = 0; c < 8; c++) {
            if (c < 7) asm volatile("cp.async.wait_group 1;" ::: "memory");
            else       asm volatile("cp.async.wait_group 0;" ::: "memory");
            __syncthreads();
            const uint32_t sb = smb + (c & 1) * GM_STG;
            #pragma unroll
            for (int ki = 0; ki < 4; ki++) {
                uint32_t a0[4], a1[4], b[4][4];
                ldsm4(a0[0], a0[1], a0[2], a0[3], sb + a_off + ki * 32);
                ldsm4(a1[0], a1[1], a1[2], a1[3], sb + a_off + 16 * 144 + ki * 32);
                #pragma unroll
                for (int nb = 0; nb < 4; nb++)
                    ldsm4(b[nb][0], b[nb][1], b[nb][2], b[nb][3],
                          sb + b_off + nb * 16 * 144 + ki * 32);
                #pragma unroll
                for (int nt = 0; nt < 8; nt++) {
                    uint32_t bb0 = b[nt >> 1][nt & 1];
                    uint32_t bb1 = b[nt >> 1][(nt & 1) + 2];
                    mma16816(acc[0][nt], a0[0], a0[1], a0[2], a0[3], bb0, bb1);
                    mma16816(acc[1][nt], a1[0], a1[1], a1[2], a1[3], bb0, bb1);
                }
            }
            __syncthreads();
            issueG(c + 2);
        }

        // epilogue: store y (fp16) + column sum/sumsq
        #pragma unroll
        for (int nt = 0; nt < 8; nt++) {
            int col = wn * 64 + nt * 8 + tig * 2;     // 0..255
            float s0 = 0.f, s1 = 0.f, q0 = 0.f, q1 = 0.f;
            #pragma unroll
            for (int mt = 0; mt < 2; mt++) {
                float c0 = acc[mt][nt][0], c1 = acc[mt][nt][1];
                float c2 = acc[mt][nt][2], c3 = acc[mt][nt][3];
                int r = i0 + wm * 32 + mt * 16 + g;
                *(__half2*)(d_yh + (size_t)r * F2DIM + col)       = __floats2half2_rn(c0, c1);
                *(__half2*)(d_yh + (size_t)(r + 8) * F2DIM + col) = __floats2half2_rn(c2, c3);
                s0 += c0 + c2;  s1 += c1 + c3;
                q0 += c0 * c0 + c2 * c2;  q1 += c1 * c1 + c3 * c3;
            }
            #pragma unroll
            for (int off = 4; off < 32; off <<= 1) {
                s0 += __shfl_xor_sync(0xffffffffu, s0, off);
                s1 += __shfl_xor_sync(0xffffffffu, s1, off);
                q0 += __shfl_xor_sync(0xffffffffu, q0, off);
                q1 += __shfl_xor_sync(0xffffffffu, q1, off);
            }
            if (lane < 4) {
                atomicAdd(&colsum[col], s0);
                atomicAdd(&colsum[col + 1], s1);
                atomicAdd(&colsq[col], q0);
                atomicAdd(&colsq[col + 1], q1);
            }
        }
        __syncthreads();
        atomicAdd(&d_sum4[tid], colsum[tid]);
        atomicAdd(&d_sq4[tid], colsq[tid]);
    }
}

// ---------------- kernel 4: BN4 + relu + W5 dot -> logits ----------------
__global__ void __launch_bounds__(256) k_final(
    const float* __restrict__ g4, const float* __restrict__ be4,
    const float* __restrict__ W5, const float* __restrict__ b5,
    float* __restrict__ out)
{
    const int lane = threadIdx.x & 31;
    const int wid  = threadIdx.x >> 5;
    float a[8], c[8], w[8];
    #pragma unroll
    for (int j = 0; j < 8; j++) {
        int col = lane * 8 + j;
        float m  = d_sum4[col] * (1.0f / BATCH);
        float v  = d_sq4[col] * (1.0f / BATCH) - m * m;
        float aa = g4[col] * rsqrtf(v + EPS_F);
        a[j] = aa;
        c[j] = be4[col] - aa * m;
        w[j] = W5[col];
    }
    float bias = b5[0];
    for (int i = blockIdx.x * 8 + wid; i < BATCH; i += gridDim.x * 8) {
        uint4 raw = *(const uint4*)(d_yh + (size_t)i * F2DIM + lane * 8);
        float2 f0 = __half22float2(*(__half2*)&raw.x);
        float2 f1 = __half22float2(*(__half2*)&raw.y);
        float2 f2 = __half22float2(*(__half2*)&raw.z);
        float2 f3 = __half22float2(*(__half2*)&raw.w);
        float accv =
            fmaxf(fmaf(a[0], f0.x, c[0]), 0.f) * w[0] +
            fmaxf(fmaf(a[1], f0.y, c[1]), 0.f) * w[1] +
            fmaxf(fmaf(a[2], f1.x, c[2]), 0.f) * w[2] +
            fmaxf(fmaf(a[3], f1.y, c[3]), 0.f) * w[3] +
            fmaxf(fmaf(a[4], f2.x, c[4]), 0.f) * w[4] +
            fmaxf(fmaf(a[5], f2.y, c[5]), 0.f) * w[5] +
            fmaxf(fmaf(a[6], f3.x, c[6]), 0.f) * w[6] +
            fmaxf(fmaf(a[7], f3.y, c[7]), 0.f) * w[7];
        #pragma unroll
        for (int off = 16; off; off >>= 1)
            accv += __shfl_xor_sync(0xffffffffu, accv, off);
        if (lane == 0) out[i] = accv + bias;
    }
}

// ---------------- launch ----------------
extern "C" void kernel_launch(void* const* d_in, const int* in_sizes, int n_in,
                              void* d_out, int out_size)
{
    (void)in_sizes; (void)n_in; (void)out_size;
    const int*   subj  = (const int*)d_in[0];
    const int*   obj   = (const int*)d_in[1];
    const int*   predi = (const int*)d_in[2];
    const float* W1    = (const float*)d_in[3];
    const float* g1    = (const float*)d_in[5];
    const float* be1   = (const float*)d_in[6];
    const float* W2    = (const float*)d_in[7];
    const float* g2    = (const float*)d_in[9];
    const float* be2   = (const float*)d_in[10];
    const float* W3    = (const float*)d_in[11];
    const float* g3    = (const float*)d_in[13];
    const float* be3   = (const float*)d_in[14];
    const float* W4    = (const float*)d_in[15];
    const float* g4    = (const float*)d_in[17];
    const float* be4   = (const float*)d_in[18];
    const float* W5    = (const float*)d_in[19];
    const float* b5    = (const float*)d_in[20];
    float* out = (float*)d_out;

    cudaFuncSetAttribute(k_gg, cudaFuncAttributeMaxDynamicSharedMemorySize, GG_SMEM);

    // zero the accumulator scratch via memset nodes (no kernel launch slots)
    void* p;
    cudaGetSymbolAddress(&p, d_cnt_s);  cudaMemsetAsync(p, 0, OBJ_DIM * 4, 0);
    cudaGetSymbolAddress(&p, d_cnt_o);  cudaMemsetAsync(p, 0, OBJ_DIM * 4, 0);
    cudaGetSymbolAddress(&p, d_cnt_p);  cudaMemsetAsync(p, 0, (PRED_DIM + 16) * 4, 0);
    cudaGetSymbolAddress(&p, d_sumb);   cudaMemsetAsync(p, 0, 3 * FDIM * 4, 0);
    cudaGetSymbolAddress(&p, d_sqb);    cudaMemsetAsync(p, 0, 3 * FDIM * 4, 0);
    cudaGetSymbolAddress(&p, d_sum4);   cudaMemsetAsync(p, 0, F2DIM * 4, 0);
    cudaGetSymbolAddress(&p, d_sq4);    cudaMemsetAsync(p, 0, F2DIM * 4, 0);
    cudaGetSymbolAddress(&p, d_flag);   cudaMemsetAsync(p, 0, NTILE * 4, 0);

    k_hist<<<BATCH / 256, 256>>>(subj, obj, predi, W4);     // kernel 0
    k_cs<<<928, 256>>>(W1, W2, W3, 448, 896);               // kernel 1
    k_coef<<<1, 512>>>(g1, be1, g2, be2, g3, be3);          // kernel 2
    k_gg<<<NTILE + LAG, 256, GG_SMEM>>>(subj, obj, predi, W1, W2, W3);  // kernel 3 <- profiled
    k_final<<<2048, 256>>>(g4, be4, W5, b5, out);           // kernel 4
}

// round 16
// speedup vs baseline: 1.0664x; 1.0664x over previous
#include <cuda_runtime.h>
#include <cuda_fp16.h>
#include <cstdint>
#include <cstddef>

#define BATCH     131072
#define FDIM      512
#define F2DIM     256
#define OBJ_DIM   100000
#define PRED_DIM  2000
#define EPS_F     1e-5f

// ---------------- device scratch (static, no allocation) ----------------
__device__ int   d_cnt_s[OBJ_DIM];
__device__ int   d_cnt_o[OBJ_DIM];
__device__ int   d_cnt_p[PRED_DIM];
__device__ __align__(16) float d_sumb[3][FDIM];
__device__ __align__(16) float d_sqb [3][FDIM];
__device__ __align__(16) __half d_W4h[F2DIM * FDIM];         // fp16 W4, row-major [256][512]
__device__ __align__(16) __half d_Af[(size_t)BATCH * FDIM];  // fused fp16 A, 128 MB
__device__ __align__(16) __half d_yh[(size_t)BATCH * F2DIM]; // pre-BN layer-4 out, fp16, 64 MB
__device__ float d_sum4[F2DIM];
__device__ float d_sq4 [F2DIM];

// ---------------- helpers ----------------
__device__ __forceinline__ uint32_t smem_u32(const void* p) {
    uint32_t a;
    asm("{ .reg .u64 t; cvta.to.shared.u64 t, %1; cvt.u32.u64 %0, t; }" : "=r"(a) : "l"(p));
    return a;
}
__device__ __forceinline__ void cp16(uint32_t dst, const void* src) {
    asm volatile("cp.async.cg.shared.global [%0], [%1], 16;" :: "r"(dst), "l"(src) : "memory");
}
__device__ __forceinline__ void cp_commit() {
    asm volatile("cp.async.commit_group;" ::: "memory");
}
__device__ __forceinline__ float relu_aff(float a, float w, float c) {
    return fmaxf(fmaf(a, w, c), 0.f);
}
__device__ __forceinline__ void ldsm4(uint32_t& r0, uint32_t& r1, uint32_t& r2, uint32_t& r3,
                                      uint32_t addr) {
    asm volatile("ldmatrix.sync.aligned.m8n8.x4.shared.b16 {%0,%1,%2,%3}, [%4];"
                 : "=r"(r0), "=r"(r1), "=r"(r2), "=r"(r3) : "r"(addr));
}
__device__ __forceinline__ void mma16816(float* d, uint32_t a0, uint32_t a1, uint32_t a2,
                                         uint32_t a3, uint32_t b0, uint32_t b1) {
    asm("mma.sync.aligned.m16n8k16.row.col.f32.f16.f16.f32 "
        "{%0,%1,%2,%3}, {%4,%5,%6,%7}, {%8,%9}, {%0,%1,%2,%3};\n"
        : "+f"(d[0]), "+f"(d[1]), "+f"(d[2]), "+f"(d[3])
        : "r"(a0), "r"(a1), "r"(a2), "r"(a3), "r"(b0), "r"(b1));
}

// ---------------- kernel 0: index histograms + W4 -> fp16 ----------------
__global__ void k_hist(const int* __restrict__ subj, const int* __restrict__ obj,
                       const int* __restrict__ predi, const float* __restrict__ W4) {
    int i = blockIdx.x * blockDim.x + threadIdx.x;
    atomicAdd(&d_cnt_s[subj[i]], 1);
    atomicAdd(&d_cnt_o[obj[i]], 1);
    atomicAdd(&d_cnt_p[predi[i]], 1);
    d_W4h[i] = __float2half_rn(W4[i]);
}

// ---------------- kernel 1: count-weighted column stats (compacted cp.async ring) ----
// Each block owns a contiguous 250-row slice, builds a local nonzero (row,cnt)
// list in smem (no global atomics), then rings 8-row stages through 3 buffers.
// Deep cp.async MLP on ONLY the ~74% nonzero rows -> DRAM-bound.
#define CS_SPAN  250
#define CS_STG   16384                        // 8 rows x 2 KB
#define CS_LIST  (3 * CS_STG)                 // int2 list[256]
#define CS_NNZ   (CS_LIST + 2048)
#define CS_SMEM  (CS_NNZ + 16)                // 51216

__global__ void __launch_bounds__(256) k_cs(const float* __restrict__ W1,
                                            const float* __restrict__ W2,
                                            const float* __restrict__ W3,
                                            int S1, int S2) {
    extern __shared__ char scs[];
    const uint32_t smb = smem_u32(scs);
    int2* list = (int2*)(scs + CS_LIST);
    int*  nnzp = (int*)(scs + CS_NNZ);
    const float* W; const int* cnt; int sel, bid, R;
    if ((int)blockIdx.x < S1)      { W = W1; cnt = d_cnt_s; sel = 0; bid = blockIdx.x;      R = OBJ_DIM; }
    else if ((int)blockIdx.x < S2) { W = W2; cnt = d_cnt_o; sel = 1; bid = blockIdx.x - S1; R = OBJ_DIM; }
    else                           { W = W3; cnt = d_cnt_p; sel = 2; bid = blockIdx.x - S2; R = PRED_DIM; }
    const int tid = threadIdx.x;
    const int r0 = bid * CS_SPAN;
    const int r1 = min(R, r0 + CS_SPAN);

    if (tid == 0) *nnzp = 0;
    __syncthreads();
    for (int r = r0 + tid; r < r1; r += 256) {
        int c = cnt[r];
        if (c) { int p = atomicAdd(nnzp, 1); list[p] = make_int2(r, c); }
    }
    __syncthreads();
    const int n = *nnzp;
    const int niter = (n + 7) >> 3;

    auto issue = [&](int i) {
        if (i < niter) {
            uint32_t dstb = smb + (i % 3) * CS_STG;
            #pragma unroll
            for (int u = 0; u < 4; u++) {
                int lin = tid + 256 * u;          // 0..1023 float4 slots
                int rr = lin >> 7, cc = lin & 127;
                int e = i * 8 + rr;
                if (e < n)
                    cp16(dstb + lin * 16, W + (size_t)list[e].x * FDIM + cc * 4);
            }
        }
        cp_commit();                               // empty group ok
    };

    const int grp = tid >> 7;                      // 0..1 : row substream
    const int t   = tid & 127;                     // float4 column
    float4 s = make_float4(0.f, 0.f, 0.f, 0.f);
    float4 q = make_float4(0.f, 0.f, 0.f, 0.f);

    issue(0); issue(1); issue(2);
    #pragma unroll 1
    for (int i = 0; i < niter; i++) {
        asm volatile("cp.async.wait_group 2;" ::: "memory");
        __syncthreads();
        const float4* st4 = (const float4*)(scs + (i % 3) * CS_STG);
        #pragma unroll
        for (int k = 0; k < 4; k++) {
            int rr = grp + k * 2;
            int e = i * 8 + rr;
            if (e < n) {
                float fc = (float)list[e].y;
                float4 v = st4[rr * 128 + t];
                s.x += fc * v.x; s.y += fc * v.y; s.z += fc * v.z; s.w += fc * v.w;
                q.x += fc * v.x * v.x; q.y += fc * v.y * v.y;
                q.z += fc * v.z * v.z; q.w += fc * v.w * v.w;
            }
        }
        __syncthreads();
        issue(i + 3);
    }
    int cb0 = t * 4;
    atomicAdd(&d_sumb[sel][cb0 + 0], s.x);
    atomicAdd(&d_sumb[sel][cb0 + 1], s.y);
    atomicAdd(&d_sumb[sel][cb0 + 2], s.z);
    atomicAdd(&d_sumb[sel][cb0 + 3], s.w);
    atomicAdd(&d_sqb[sel][cb0 + 0], q.x);
    atomicAdd(&d_sqb[sel][cb0 + 1], q.y);
    atomicAdd(&d_sqb[sel][cb0 + 2], q.z);
    atomicAdd(&d_sqb[sel][cb0 + 3], q.w);
}

// ---------------- kernel 2: cp.async-pipelined gather + BN-relu -> fp16 A ----------------
// PROVEN at 72% DRAM — unchanged.
#define G_ROWS   64
#define G_SR     4
#define G_NSTG   16
#define STG_B    (G_SR * 3 * FDIM * 4)        // 24576 bytes per stage
#define G_COEF   (3 * STG_B)                  // 73728
#define G_IDX    (G_COEF + 12288)             // 86016
#define G_SMEM   (G_IDX + 768)                // 86784

__global__ void __launch_bounds__(256) k_gather(
    const int* __restrict__ subj, const int* __restrict__ obj, const int* __restrict__ predi,
    const float* __restrict__ W1, const float* __restrict__ W2, const float* __restrict__ W3,
    const float* __restrict__ g1, const float* __restrict__ be1,
    const float* __restrict__ g2, const float* __restrict__ be2,
    const float* __restrict__ g3, const float* __restrict__ be3)
{
    extern __shared__ char sg[];
    const uint32_t smb = smem_u32(sg);
    float* cA = (float*)(sg + G_COEF);          // [3*512]
    float* cC = (float*)(sg + G_COEF + 6144);
    int*   idxs = (int*)(sg + G_IDX);           // [3][64]
    const int tid = threadIdx.x;
    const int i0 = blockIdx.x * G_ROWS;

    if (tid < G_ROWS) {
        idxs[tid]       = subj[i0 + tid];
        idxs[64 + tid]  = obj[i0 + tid];
        idxs[128 + tid] = predi[i0 + tid];
    }
    for (int t = tid; t < FDIM; t += 256) {
        float m, v, a;
        m = d_sumb[0][t] * (1.f / BATCH); v = d_sqb[0][t] * (1.f / BATCH) - m * m;
        a = g1[t] * rsqrtf(v + EPS_F); cA[t] = a;          cC[t] = be1[t] - a * m;
        m = d_sumb[1][t] * (1.f / BATCH); v = d_sqb[1][t] * (1.f / BATCH) - m * m;
        a = g2[t] * rsqrtf(v + EPS_F); cA[512 + t] = a;    cC[512 + t] = be2[t] - a * m;
        m = d_sumb[2][t] * (1.f / BATCH); v = d_sqb[2][t] * (1.f / BATCH) - m * m;
        a = g3[t] * rsqrtf(v + EPS_F); cA[1024 + t] = a;   cC[1024 + t] = be3[t] - a * m;
    }
    __syncthreads();

    const int c4 = tid & 127;
    const int rs0 = tid >> 7;          // 0..1
    const int k0 = c4 * 4;
    const float4 A1 = *(const float4*)&cA[k0],        C1 = *(const float4*)&cC[k0];
    const float4 A2 = *(const float4*)&cA[512 + k0],  C2 = *(const float4*)&cC[512 + k0];
    const float4 A3 = *(const float4*)&cA[1024 + k0], C3 = *(const float4*)&cC[1024 + k0];

    auto issue = [&](int s) {
        int buf = s % 3;
        uint32_t dstb = smb + buf * STG_B;
        #pragma unroll
        for (int u = 0; u < 6; u++) {
            int lin = tid + 256 * u;            // 0..1535 float4 slots
            int ris = lin / 384;                // row in stage
            int rem = lin - ris * 384;
            int tab = rem >> 7;                 // table 0..2
            int cc  = rem & 127;                // float4 col
            int gi  = idxs[tab * 64 + s * G_SR + ris];
            const float* Wt = (tab == 0) ? W1 : (tab == 1) ? W2 : W3;
            cp16(dstb + lin * 16, Wt + (size_t)gi * FDIM + cc * 4);
        }
        cp_commit();
    };

    issue(0); issue(1);
    #pragma unroll 1
    for (int s = 0; s < G_NSTG; s++) {
        if (s + 2 < G_NSTG) issue(s + 2);
        if (s < G_NSTG - 2)       asm volatile("cp.async.wait_group 2;" ::: "memory");
        else if (s == G_NSTG - 2) asm volatile("cp.async.wait_group 1;" ::: "memory");
        else                      asm volatile("cp.async.wait_group 0;" ::: "memory");
        __syncthreads();
        const float4* st4 = (const float4*)(sg + (s % 3) * STG_B);
        #pragma unroll
        for (int rr = 0; rr < 2; rr++) {
            int ris = rs0 + rr * 2;
            int row = i0 + s * G_SR + ris;
            float4 w1 = st4[ris * 384 + c4];
            float4 w2 = st4[ris * 384 + 128 + c4];
            float4 w3 = st4[ris * 384 + 256 + c4];
            float f0 = relu_aff(A1.x, w1.x, C1.x) + relu_aff(A2.x, w2.x, C2.x) + relu_aff(A3.x, w3.x, C3.x);
            float f1 = relu_aff(A1.y, w1.y, C1.y) + relu_aff(A2.y, w2.y, C2.y) + relu_aff(A3.y, w3.y, C3.y);
            float f2 = relu_aff(A1.z, w1.z, C1.z) + relu_aff(A2.z, w2.z, C2.z) + relu_aff(A3.z, w3.z, C3.z);
            float f3 = relu_aff(A1.w, w1.w, C1.w) + relu_aff(A2.w, w2.w, C2.w) + relu_aff(A3.w, w3.w, C3.w);
            __half2 h0 = __floats2half2_rn(f0, f1);
            __half2 h1 = __floats2half2_rn(f2, f3);
            uint2 u;
            u.x = *(unsigned*)&h0;
            u.y = *(unsigned*)&h1;
            *(uint2*)(d_Af + (size_t)row * FDIM + k0) = u;
        }
        __syncthreads();
    }
}

// ---------------- kernel 3: GEMM y = A * W4^T (ldmatrix + HMMA, 2 CTAs/SM) ----------------
// 256 threads, 128x128 tile, KC=64, 2-stage ring -> 75 KB smem -> 2 CTAs/SM.
#define KC3     64
#define SROW3   144                          // 72 halfs (64 + 8 pad); 9x16B -> LDSM conflict-free
#define A3_SZ   (128 * SROW3)                // 18432
#define B3_SZ   (128 * SROW3)                // 18432
#define STG3    (A3_SZ + B3_SZ)              // 36864 per stage
#define SM3_SUM (2 * STG3)                   // 73728
#define SM3_SQ  (SM3_SUM + 512)
#define SM3_TOT (SM3_SQ + 512)               // 74752

__global__ void __launch_bounds__(256, 2) k_gemm() {
    extern __shared__ char sm[];
    const uint32_t smb = smem_u32(sm);
    const int tid = threadIdx.x, lane = tid & 31, wid = tid >> 5;
    const int cid = blockIdx.x & 1;           // N half
    const int i0  = (blockIdx.x >> 1) * 128;  // row tile
    const int n0  = cid * 128;                // col base
    float* colsum = (float*)(sm + SM3_SUM);   // [128]
    float* colsq  = (float*)(sm + SM3_SQ);    // [128]
    if (tid < 128) colsum[tid] = 0.f;
    else colsq[tid - 128] = 0.f;

    const int wm = wid >> 1, wn = wid & 1, g = lane >> 2, tig = lane & 3;

    auto issue = [&](int c) {
        if (c < 8) {
            uint32_t base = smb + (c & 1) * STG3;
            #pragma unroll
            for (int u = 0; u < 4; u++) {       // A: 128 rows x 64 halfs = 1024 slots
                int idx = tid + 256 * u;
                int row = idx >> 3, o = idx & 7;
                cp16(base + row * SROW3 + o * 16,
                     d_Af + (size_t)(i0 + row) * FDIM + c * KC3 + o * 8);
            }
            #pragma unroll
            for (int u = 0; u < 4; u++) {       // B: 128 rows x 64 halfs = 1024 slots
                int idx = tid + 256 * u;
                int n = idx >> 3, o = idx & 7;
                cp16(base + A3_SZ + n * SROW3 + o * 16,
                     d_W4h + (n0 + n) * FDIM + c * KC3 + o * 8);
            }
        }
        cp_commit();
    };

    float acc[2][8][4];
    #pragma unroll
    for (int mt = 0; mt < 2; mt++)
        #pragma unroll
        for (int nt = 0; nt < 8; nt++)
            #pragma unroll
            for (int u = 0; u < 4; u++) acc[mt][nt][u] = 0.f;

    const int lm_r = lane & 15;
    const int lm_c = (lane >> 4) * 16;
    const uint32_t a_off = (wm * 32 + lm_r) * SROW3 + lm_c;
    const uint32_t b_off = A3_SZ + (wn * 64 + lm_r) * SROW3 + lm_c;

    issue(0); issue(1);
    #pragma unroll 1
    for (int c = 0; c < 8; c++) {
        if (c < 7) asm volatile("cp.async.wait_group 1;" ::: "memory");
        else       asm volatile("cp.async.wait_group 0;" ::: "memory");
        __syncthreads();
        const uint32_t sb = smb + (c & 1) * STG3;
        #pragma unroll
        for (int ki = 0; ki < 4; ki++) {
            uint32_t a0[4], a1[4], b[4][4];
            ldsm4(a0[0], a0[1], a0[2], a0[3], sb + a_off + ki * 32);
            ldsm4(a1[0], a1[1], a1[2], a1[3], sb + a_off + 16 * SROW3 + ki * 32);
            #pragma unroll
            for (int nb = 0; nb < 4; nb++)
                ldsm4(b[nb][0], b[nb][1], b[nb][2], b[nb][3],
                      sb + b_off + nb * 16 * SROW3 + ki * 32);
            #pragma unroll
            for (int nt = 0; nt < 8; nt++) {
                uint32_t bb0 = b[nt >> 1][nt & 1];
                uint32_t bb1 = b[nt >> 1][(nt & 1) + 2];
                mma16816(acc[0][nt], a0[0], a0[1], a0[2], a0[3], bb0, bb1);
                mma16816(acc[1][nt], a1[0], a1[1], a1[2], a1[3], bb0, bb1);
            }
        }
        __syncthreads();
        issue(c + 2);
    }

    // epilogue: store y (fp16) + column sum/sumsq (fp32 from accs)
    #pragma unroll
    for (int nt = 0; nt < 8; nt++) {
        int lc = wn * 64 + nt * 8 + tig * 2;      // local col 0..127
        int col = n0 + lc;
        float s0 = 0.f, s1 = 0.f, q0 = 0.f, q1 = 0.f;
        #pragma unroll
        for (int mt = 0; mt < 2; mt++) {
            float c0 = acc[mt][nt][0], c1 = acc[mt][nt][1];
            float c2 = acc[mt][nt][2], c3 = acc[mt][nt][3];
            int r = i0 + wm * 32 + mt * 16 + g;
            *(__half2*)(d_yh + (size_t)r * F2DIM + col)       = __floats2half2_rn(c0, c1);
            *(__half2*)(d_yh + (size_t)(r + 8) * F2DIM + col) = __floats2half2_rn(c2, c3);
            s0 += c0 + c2;  s1 += c1 + c3;
            q0 += c0 * c0 + c2 * c2;  q1 += c1 * c1 + c3 * c3;
        }
        #pragma unroll
        for (int off = 4; off < 32; off <<= 1) {
            s0 += __shfl_xor_sync(0xffffffffu, s0, off);
            s1 += __shfl_xor_sync(0xffffffffu, s1, off);
            q0 += __shfl_xor_sync(0xffffffffu, q0, off);
            q1 += __shfl_xor_sync(0xffffffffu, q1, off);
        }
        if (lane < 4) {
            atomicAdd(&colsum[lc], s0);
            atomicAdd(&colsum[lc + 1], s1);
            atomicAdd(&colsq[lc], q0);
            atomicAdd(&colsq[lc + 1], q1);
        }
    }
    __syncthreads();
    if (tid < 128) atomicAdd(&d_sum4[n0 + tid], colsum[tid]);
    else atomicAdd(&d_sq4[n0 + tid - 128], colsq[tid - 128]);
}

// ---------------- kernel 4: BN4 + relu + W5 dot -> logits ----------------
__global__ void __launch_bounds__(256) k_final(
    const float* __restrict__ g4, const float* __restrict__ be4,
    const float* __restrict__ W5, const float* __restrict__ b5,
    float* __restrict__ out)
{
    const int lane = threadIdx.x & 31;
    const int wid  = threadIdx.x >> 5;
    float a[8], c[8], w[8];
    #pragma unroll
    for (int j = 0; j < 8; j++) {
        int col = lane * 8 + j;
        float m  = d_sum4[col] * (1.0f / BATCH);
        float v  = d_sq4[col] * (1.0f / BATCH) - m * m;
        float aa = g4[col] * rsqrtf(v + EPS_F);
        a[j] = aa;
        c[j] = be4[col] - aa * m;
        w[j] = W5[col];
    }
    float bias = b5[0];
    for (int i = blockIdx.x * 8 + wid; i < BATCH; i += gridDim.x * 8) {
        uint4 raw = *(const uint4*)(d_yh + (size_t)i * F2DIM + lane * 8);
        float2 f0 = __half22float2(*(__half2*)&raw.x);
        float2 f1 = __half22float2(*(__half2*)&raw.y);
        float2 f2 = __half22float2(*(__half2*)&raw.z);
        float2 f3 = __half22float2(*(__half2*)&raw.w);
        float accv =
            fmaxf(fmaf(a[0], f0.x, c[0]), 0.f) * w[0] +
            fmaxf(fmaf(a[1], f0.y, c[1]), 0.f) * w[1] +
            fmaxf(fmaf(a[2], f1.x, c[2]), 0.f) * w[2] +
            fmaxf(fmaf(a[3], f1.y, c[3]), 0.f) * w[3] +
            fmaxf(fmaf(a[4], f2.x, c[4]), 0.f) * w[4] +
            fmaxf(fmaf(a[5], f2.y, c[5]), 0.f) * w[5] +
            fmaxf(fmaf(a[6], f3.x, c[6]), 0.f) * w[6] +
            fmaxf(fmaf(a[7], f3.y, c[7]), 0.f) * w[7];
        #pragma unroll
        for (int off = 16; off; off >>= 1)
            accv += __shfl_xor_sync(0xffffffffu, accv, off);
        if (lane == 0) out[i] = accv + bias;
    }
}

// ---------------- launch ----------------
extern "C" void kernel_launch(void* const* d_in, const int* in_sizes, int n_in,
                              void* d_out, int out_size)
{
    (void)in_sizes; (void)n_in; (void)out_size;
    const int*   subj  = (const int*)d_in[0];
    const int*   obj   = (const int*)d_in[1];
    const int*   predi = (const int*)d_in[2];
    const float* W1    = (const float*)d_in[3];
    const float* g1    = (const float*)d_in[5];
    const float* be1   = (const float*)d_in[6];
    const float* W2    = (const float*)d_in[7];
    const float* g2    = (const float*)d_in[9];
    const float* be2   = (const float*)d_in[10];
    const float* W3    = (const float*)d_in[11];
    const float* g3    = (const float*)d_in[13];
    const float* be3   = (const float*)d_in[14];
    const float* W4    = (const float*)d_in[15];
    const float* g4    = (const float*)d_in[17];
    const float* be4   = (const float*)d_in[18];
    const float* W5    = (const float*)d_in[19];
    const float* b5    = (const float*)d_in[20];
    float* out = (float*)d_out;

    cudaFuncSetAttribute(k_cs, cudaFuncAttributeMaxDynamicSharedMemorySize, CS_SMEM);
    cudaFuncSetAttribute(k_gather, cudaFuncAttributeMaxDynamicSharedMemorySize, G_SMEM);
    cudaFuncSetAttribute(k_gemm, cudaFuncAttributeMaxDynamicSharedMemorySize, SM3_TOT);

    // zero the accumulator scratch via memset nodes (no kernel launch slots)
    void* p;
    cudaGetSymbolAddress(&p, d_cnt_s);  cudaMemsetAsync(p, 0, OBJ_DIM * 4, 0);
    cudaGetSymbolAddress(&p, d_cnt_o);  cudaMemsetAsync(p, 0, OBJ_DIM * 4, 0);
    cudaGetSymbolAddress(&p, d_cnt_p);  cudaMemsetAsync(p, 0, PRED_DIM * 4, 0);
    cudaGetSymbolAddress(&p, d_sumb);   cudaMemsetAsync(p, 0, 3 * FDIM * 4, 0);
    cudaGetSymbolAddress(&p, d_sqb);    cudaMemsetAsync(p, 0, 3 * FDIM * 4, 0);
    cudaGetSymbolAddress(&p, d_sum4);   cudaMemsetAsync(p, 0, F2DIM * 4, 0);
    cudaGetSymbolAddress(&p, d_sq4);    cudaMemsetAsync(p, 0, F2DIM * 4, 0);

    k_hist<<<BATCH / 256, 256>>>(subj, obj, predi, W4);     // kernel 0
    // W1: blocks [0,400), W2: [400,800), W3: [800,808) — 250 rows per block
    k_cs<<<808, 256, CS_SMEM>>>(W1, W2, W3, 400, 800);      // kernel 1
    k_gather<<<BATCH / G_ROWS, 256, G_SMEM>>>(subj, obj, predi, W1, W2, W3,
                                              g1, be1, g2, be2, g3, be3);  // kernel 2
    k_gemm<<<(BATCH / 128) * 2, 256, SM3_TOT>>>();          // kernel 3 <- profile target
    k_final<<<2048, 256>>>(g4, be4, W5, b5, out);           // kernel 4
}